// round 12
// baseline (speedup 1.0000x reference)
#include <cuda_runtime.h>
#include <cstdint>

// ============================================================================
// LSTM autoencoder  B=256 T=512 D=128 H=256
// Persistent-kernel: 128 CTAs x 128 threads, 1 grid barrier per phase.
// f32x2 packed-FMA inner loop (2 rows x 8 gates per thread).
// ============================================================================

#define NB 128          // CTAs (one per SM, all resident)
#define NT 128          // threads per CTA
#define HB 65536        // 256*256 floats per h-state buffer

// ---- device-global scratch (no allocation allowed) -------------------------
__device__ float g_Wenc0[384 * 1024];   // [k][gatecol]  k<128: Wih(x), else Whh(h1)
__device__ float g_Wenc1[512 * 1024];   // k<256: Wih(h1), else Whh(h2)
__device__ float g_Wdec0[512 * 1024];   // k<256: W' = d_Wih0 @ fc_W, else Whh(h1)
__device__ float g_Wdec1[512 * 1024];   // k<256: Wih(h1), else Whh(h2)
__device__ float g_benc0[1024];
__device__ float g_benc1[1024];
__device__ float g_bdec0[1024];         // bih+bhh + d_Wih0@fc_b   (t>=1)
__device__ float g_bdec0t0[1024];       // bih+bhh                 (t==0, zero input)
__device__ float g_bdec1[1024];
__device__ float g_fcWT[256 * 128];     // fc_W transposed: [u][d]

__device__ float g_h1e[2][HB];
__device__ float g_h2e[2][HB];
__device__ float g_h1d[2][HB];
__device__ float g_zero[HB];
__device__ float g_hist[512ll * HB];    // decoder h2 history [t][b][u]  (128 MB)

__device__ unsigned g_barCnt = 0;
__device__ unsigned g_barGen = 0;

// ---- helpers ---------------------------------------------------------------
__device__ __forceinline__ float sigf(float v) { return 1.0f / (1.0f + __expf(-v)); }

__device__ __forceinline__ unsigned long long splat2(float v) {
    unsigned long long r;
    unsigned u = __float_as_uint(v);
    asm("mov.b64 %0, {%1, %1};" : "=l"(r) : "r"(u));
    return r;
}
__device__ __forceinline__ void ffma2(unsigned long long& d,
                                      unsigned long long a, unsigned long long b) {
    asm("fma.rn.f32x2 %0, %1, %2, %0;" : "+l"(d) : "l"(a), "l"(b));
}
__device__ __forceinline__ float2 unpack2(unsigned long long v) {
    float2 f;
    asm("mov.b64 {%0, %1}, %2;" : "=f"(f.x), "=f"(f.y) : "l"(v));
    return f;
}

__device__ __forceinline__ void gridbar() {
    __syncthreads();
    if (threadIdx.x == 0) {
        unsigned gen = *(volatile unsigned*)&g_barGen;
        __threadfence();
        if (atomicAdd(&g_barCnt, 1u) == NB - 1) {
            atomicExch(&g_barCnt, 0u);
            __threadfence();
            atomicAdd(&g_barGen, 1u);
        } else {
            while (*(volatile unsigned*)&g_barGen == gen) { }
        }
        __threadfence();
    }
    __syncthreads();
}

#define CP16(dst_generic, src) do {                                         \
    unsigned _d = (unsigned)__cvta_generic_to_shared(dst_generic);          \
    asm volatile("cp.async.cg.shared.global [%0], [%1], 16;\n"              \
                 :: "r"(_d), "l"(src));                                     \
} while (0)

// smem layout (dynamic): As[2][32][68] then Bs[2][64][64]
#define AS_STRIDE 68
#define AS_BUF   2176       // 32*68
#define BS_BUF   4096       // 64*64
#define SMEM_FLOATS (2*AS_BUF + 2*BS_BUF)   // 12544 floats = 50176 B

// stage one 64-wide k tile of A (activations) and B (weights) into smem
__device__ __forceinline__ void stage_tile(
    int tile, int buf,
    const float* __restrict__ a0, long sa0, int k0len,
    const float* __restrict__ a1, long sa1,
    const float* __restrict__ W,
    float* As, float* Bs, int rb, int gb, int tid)
{
    int kbase = tile << 6;
    const float* sA; long st; int kl;
    if (kbase < k0len) { sA = a0; st = sa0; kl = kbase; }
    else               { sA = a1; st = sa1; kl = kbase - k0len; }
#pragma unroll
    for (int j = 0; j < 4; j++) {
        int idx = tid + j * NT;              // 0..511
        int r = idx >> 4, kq = idx & 15;
        const float* src = sA + (long)(rb * 32 + r) * st + kl + kq * 4;
        CP16(As + buf * AS_BUF + r * AS_STRIDE + kq * 4, src);
    }
#pragma unroll
    for (int j = 0; j < 8; j++) {
        int idx = tid + j * NT;              // 0..1023
        int kk = idx >> 4, gq = idx & 15;
        const float* src = W + (long)(kbase + kk) * 1024 + gb * 64 + gq * 4;
        CP16(Bs + buf * BS_BUF + kk * 64 + gq * 4, src);
    }
    asm volatile("cp.async.commit_group;\n");
}

// one LSTM cell phase: gates[256x1024] = A[256xK] @ W[Kx1024] + b ; nonlinearity
// thread tile: 2 rows x 8 gates (gate-quads tx and tx+8)
__device__ __forceinline__ void lstm_phase(
    const float* __restrict__ a0, long sa0, int k0len,
    const float* __restrict__ a1, long sa1,
    const float* __restrict__ W, const float* __restrict__ bias,
    int K, float* __restrict__ hout, float* c,
    float* As, float* Bs, int rb, int gb, int tx, int ty, int tid)
{
    unsigned long long acc00if = 0, acc00go = 0, acc01if = 0, acc01go = 0;
    unsigned long long acc10if = 0, acc10go = 0, acc11if = 0, acc11go = 0;
    int nt = K >> 6;

    stage_tile(0, 0, a0, sa0, k0len, a1, sa1, W, As, Bs, rb, gb, tid);

    for (int tl = 0; tl < nt; tl++) {
        if (tl + 1 < nt) {
            stage_tile(tl + 1, (tl + 1) & 1, a0, sa0, k0len, a1, sa1, W, As, Bs, rb, gb, tid);
            asm volatile("cp.async.wait_group 1;\n");
        } else {
            asm volatile("cp.async.wait_group 0;\n");
        }
        __syncthreads();

        const float* Asb = As + (tl & 1) * AS_BUF + (ty * 2) * AS_STRIDE;
        const float* Bsb = Bs + (tl & 1) * BS_BUF + tx * 4;
#pragma unroll 2
        for (int k = 0; k < 64; k += 4) {
            float4 av0 = *(const float4*)(Asb + k);
            float4 av1 = *(const float4*)(Asb + AS_STRIDE + k);
#define STEP(KK, AC)                                                        \
            {                                                               \
                const float* bp = Bsb + (k + KK) * 64;                      \
                ulonglong2 bl = *(const ulonglong2*)bp;                     \
                ulonglong2 bh = *(const ulonglong2*)(bp + 32);              \
                unsigned long long s0 = splat2(av0.AC);                     \
                unsigned long long s1 = splat2(av1.AC);                     \
                ffma2(acc00if, s0, bl.x); ffma2(acc00go, s0, bl.y);         \
                ffma2(acc01if, s0, bh.x); ffma2(acc01go, s0, bh.y);         \
                ffma2(acc10if, s1, bl.x); ffma2(acc10go, s1, bl.y);         \
                ffma2(acc11if, s1, bh.x); ffma2(acc11go, s1, bh.y);         \
            }
            STEP(0, x) STEP(1, y) STEP(2, z) STEP(3, w)
#undef STEP
        }
        __syncthreads();
    }

    // epilogue: each acc pair = (i,f) / (g,o) of one unit; LSTM nonlinearity
    const float* bq = bias + gb * 64 + tx * 4;
    float4 bv0 = *(const float4*)bq;          // quad tx
    float4 bv1 = *(const float4*)(bq + 32);   // quad tx+8
    int row0 = rb * 32 + ty * 2;
    int col0 = gb * 16 + tx;
#define CELL(AIF, AGO, BV, CI, ROW, COL)                                \
    {                                                                   \
        float2 pif = unpack2(AIF);                                      \
        float2 pgo = unpack2(AGO);                                      \
        float iv = pif.x + BV.x, fv = pif.y + BV.y;                     \
        float gv = pgo.x + BV.z, ov = pgo.y + BV.w;                     \
        float cn = sigf(fv) * c[CI] + sigf(iv) * tanhf(gv);             \
        c[CI] = cn;                                                     \
        hout[(ROW) * 256 + (COL)] = sigf(ov) * tanhf(cn);               \
    }
    CELL(acc00if, acc00go, bv0, 0, row0,     col0)
    CELL(acc01if, acc01go, bv1, 1, row0,     col0 + 8)
    CELL(acc10if, acc10go, bv0, 2, row0 + 1, col0)
    CELL(acc11if, acc11go, bv1, 3, row0 + 1, col0 + 8)
#undef CELL
}

// ---- persistent kernel ------------------------------------------------------
__global__ void __launch_bounds__(NT, 1) lstm_persistent(const float* __restrict__ x)
{
    extern __shared__ float sm[];
    float* As = sm;
    float* Bs = sm + 2 * AS_BUF;

    int tid = threadIdx.x, bid = blockIdx.x;
    int rb = bid & 7;        // row block  (8 x 32 rows)
    int gb = bid >> 3;       // gate block (16 x 64 gate cols)
    int tx = tid & 7;        // gate-quad pair index (quads tx, tx+8)
    int ty = tid >> 3;       // row pair index (rows 2ty, 2ty+1)

    // zero-init state buffers
    for (int i = bid * NT + tid; i < HB; i += NB * NT) {
        g_h1e[0][i] = 0.f; g_h1e[1][i] = 0.f;
        g_h2e[0][i] = 0.f; g_h2e[1][i] = 0.f;
        g_h1d[0][i] = 0.f; g_h1d[1][i] = 0.f;
        g_zero[i]   = 0.f;
    }
    gridbar();

    float c1e[4] = {0.f,0.f,0.f,0.f};
    float c2e[4] = {0.f,0.f,0.f,0.f};

    // ---------------- encoder ----------------
    for (int t = 0; t < 512; t++) {
        int cur = t & 1, prv = cur ^ 1;
        lstm_phase(x + (long)t * 128, 65536L, 128, g_h1e[prv], 256L,
                   g_Wenc0, g_benc0, 384, g_h1e[cur], c1e,
                   As, Bs, rb, gb, tx, ty, tid);
        gridbar();
        lstm_phase(g_h1e[cur], 256L, 256, g_h2e[prv], 256L,
                   g_Wenc1, g_benc1, 512, g_h2e[cur], c2e,
                   As, Bs, rb, gb, tx, ty, tid);
        gridbar();
    }

    // decoder initial states = encoder final states (same thread->cell mapping)
    float c1d[4], c2d[4];
#pragma unroll
    for (int rr = 0; rr < 4; rr++) { c1d[rr] = c1e[rr]; c2d[rr] = c2e[rr]; }

    // ---------------- decoder ----------------
    for (int t = 0; t < 512; t++) {
        int cur = t & 1, prv = cur ^ 1;
        const float* in0 = (t == 0) ? g_zero    : (g_hist + (long)(t - 1) * HB);
        const float* h1p = (t == 0) ? g_h1e[1]  : g_h1d[prv];
        const float* h2p = (t == 0) ? g_h2e[1]  : (g_hist + (long)(t - 1) * HB);
        const float* b0  = (t == 0) ? g_bdec0t0 : g_bdec0;

        lstm_phase(in0, 256L, 256, h1p, 256L,
                   g_Wdec0, b0, 512, g_h1d[cur], c1d,
                   As, Bs, rb, gb, tx, ty, tid);
        gridbar();
        lstm_phase(g_h1d[cur], 256L, 256, h2p, 256L,
                   g_Wdec1, g_bdec1, 512, g_hist + (long)t * HB, c2d,
                   As, Bs, rb, gb, tx, ty, tid);
        gridbar();
    }
}

// ---- prep kernels -----------------------------------------------------------
// permute weights into [k][gatecol] with gatecol = 4*unit + gate  (gate: i,f,g,o)
__global__ void prep_std(const float* __restrict__ Wih, const float* __restrict__ Whh,
                         const float* __restrict__ bih, const float* __restrict__ bhh,
                         int inDim, int which)
{
    float* Wd = (which == 0) ? g_Wenc0 : (which == 1) ? g_Wenc1 : g_Wdec1;
    float* bd = (which == 0) ? g_benc0 : (which == 1) ? g_benc1 : g_bdec1;
    int K = inDim + 256;
    int idx = blockIdx.x * 256 + threadIdx.x;
    if (idx < K * 1024) {
        int k = idx >> 10, ccol = idx & 1023;
        int u = ccol >> 2, j = ccol & 3;
        int sr = j * 256 + u;
        Wd[idx] = (k < inDim) ? Wih[sr * inDim + k] : Whh[sr * 256 + (k - inDim)];
    }
    if (idx < 1024) {
        int u = idx >> 2, j = idx & 3;
        int sr = j * 256 + u;
        bd[idx] = bih[sr] + bhh[sr];
    }
}

// decoder layer 0: fold fc feedback:  W' = d_Wih0 @ fc_W,  b' += d_Wih0 @ fc_b
__global__ void prep_dec0(const float* __restrict__ Wih, const float* __restrict__ Whh,
                          const float* __restrict__ bih, const float* __restrict__ bhh,
                          const float* __restrict__ fcW, const float* __restrict__ fcb)
{
    int idx = blockIdx.x * 256 + threadIdx.x;
    if (idx < 512 * 1024) {
        int k = idx >> 10, ccol = idx & 1023;
        int u = ccol >> 2, j = ccol & 3;
        int sr = j * 256 + u;
        float v;
        if (k < 256) {
            float s = 0.f;
            for (int jj = 0; jj < 128; jj++)
                s += Wih[sr * 128 + jj] * fcW[jj * 256 + k];
            v = s;
        } else {
            v = Whh[sr * 256 + (k - 256)];
        }
        g_Wdec0[idx] = v;
    }
    if (idx < 1024) {
        int u = idx >> 2, j = idx & 3;
        int sr = j * 256 + u;
        float bb = bih[sr] + bhh[sr];
        g_bdec0t0[idx] = bb;
        float s = 0.f;
        for (int jj = 0; jj < 128; jj++)
            s += Wih[sr * 128 + jj] * fcb[jj];
        g_bdec0[idx] = bb + s;
    }
}

__global__ void prep_fcwt(const float* __restrict__ fcW)
{
    int idx = blockIdx.x * 256 + threadIdx.x;    // 32768
    if (idx < 256 * 128) {
        int u = idx >> 7, d = idx & 127;
        g_fcWT[idx] = fcW[d * 256 + u];
    }
}

// ---- final output GEMM:  y[b][t][:] = hist[t][b][:] @ fc_W^T + fc_b ---------
__global__ void __launch_bounds__(256) out_gemm(const float* __restrict__ fcb,
                                                float* __restrict__ out)
{
    __shared__ float As[32 * 64];
    __shared__ float Bs[64 * 128];
    int tid = threadIdx.x;
    long rowBase = (long)blockIdx.x * 32;   // global row g = t*256 + b
    int dx = tid & 31;   // d quad
    int ry = tid >> 5;   // 8 -> 4 rows each
    float acc[4][4] = {};
    for (int kb = 0; kb < 256; kb += 64) {
        __syncthreads();
#pragma unroll
        for (int j = 0; j < 2; j++) {
            int idx = tid + j * 256;  int r = idx >> 4, kq = idx & 15;
            *(float4*)&As[r * 64 + kq * 4] =
                *(const float4*)&g_hist[(rowBase + r) * 256 + kb + kq * 4];
        }
#pragma unroll
        for (int j = 0; j < 8; j++) {
            int idx = tid + j * 256;  int k = idx >> 5, dq = idx & 31;
            *(float4*)&Bs[k * 128 + dq * 4] =
                *(const float4*)&g_fcWT[(kb + k) * 128 + dq * 4];
        }
        __syncthreads();
#pragma unroll 4
        for (int k = 0; k < 64; k++) {
            float4 b = *(const float4*)&Bs[k * 128 + dx * 4];
#pragma unroll
            for (int rr = 0; rr < 4; rr++) {
                float a = As[(ry * 4 + rr) * 64 + k];
                acc[rr][0] += a * b.x; acc[rr][1] += a * b.y;
                acc[rr][2] += a * b.z; acc[rr][3] += a * b.w;
            }
        }
    }
    float4 bb = *(const float4*)&fcb[dx * 4];
#pragma unroll
    for (int rr = 0; rr < 4; rr++) {
        long g = rowBase + ry * 4 + rr;
        long b = g & 255, t = g >> 8;
        float4 v = make_float4(acc[rr][0] + bb.x, acc[rr][1] + bb.y,
                               acc[rr][2] + bb.z, acc[rr][3] + bb.w);
        *(float4*)&out[(b * 512 + t) * 128 + dx * 4] = v;
    }
}

// ---- launch -----------------------------------------------------------------
extern "C" void kernel_launch(void* const* d_in, const int* in_sizes, int n_in,
                              void* d_out, int out_size)
{
    const float* x      = (const float*)d_in[0];
    const float* eWih0  = (const float*)d_in[1];
    const float* eWhh0  = (const float*)d_in[2];
    const float* ebih0  = (const float*)d_in[3];
    const float* ebhh0  = (const float*)d_in[4];
    const float* eWih1  = (const float*)d_in[5];
    const float* eWhh1  = (const float*)d_in[6];
    const float* ebih1  = (const float*)d_in[7];
    const float* ebhh1  = (const float*)d_in[8];
    const float* dWih0  = (const float*)d_in[9];
    const float* dWhh0  = (const float*)d_in[10];
    const float* dbih0  = (const float*)d_in[11];
    const float* dbhh0  = (const float*)d_in[12];
    const float* dWih1  = (const float*)d_in[13];
    const float* dWhh1  = (const float*)d_in[14];
    const float* dbih1  = (const float*)d_in[15];
    const float* dbhh1  = (const float*)d_in[16];
    const float* fcW    = (const float*)d_in[17];
    const float* fcb    = (const float*)d_in[18];
    float* out = (float*)d_out;

    prep_std<<<1536, 256>>>(eWih0, eWhh0, ebih0, ebhh0, 128, 0);
    prep_std<<<2048, 256>>>(eWih1, eWhh1, ebih1, ebhh1, 256, 1);
    prep_std<<<2048, 256>>>(dWih1, dWhh1, dbih1, dbhh1, 256, 2);
    prep_dec0<<<2048, 256>>>(dWih0, dWhh0, dbih0, dbhh0, fcW, fcb);
    prep_fcwt<<<128, 256>>>(fcW);

    cudaFuncSetAttribute(lstm_persistent,
                         cudaFuncAttributeMaxDynamicSharedMemorySize,
                         SMEM_FLOATS * 4);
    lstm_persistent<<<NB, NT, SMEM_FLOATS * 4>>>(x);

    out_gemm<<<4096, 256>>>(fcb, out);
}

// round 13
// speedup vs baseline: 1.0016x; 1.0016x over previous
#include <cuda_runtime.h>
#include <cstdint>

// ============================================================================
// LSTM autoencoder  B=256 T=512 D=128 H=256
// Persistent-kernel: 128 CTAs x 128 threads, 1 grid barrier per phase.
// f32x2 packed-FMA inner loop (2 rows x 8 gates per thread).
// ============================================================================

#define NB 128          // CTAs (one per SM, all resident)
#define NT 128          // threads per CTA
#define HB 65536        // 256*256 floats per h-state buffer

// ---- device-global scratch (no allocation allowed) -------------------------
__device__ float g_Wenc0[384 * 1024];   // [k][gatecol]  k<128: Wih(x), else Whh(h1)
__device__ float g_Wenc1[512 * 1024];   // k<256: Wih(h1), else Whh(h2)
__device__ float g_Wdec0[512 * 1024];   // k<256: W' = d_Wih0 @ fc_W, else Whh(h1)
__device__ float g_Wdec1[512 * 1024];   // k<256: Wih(h1), else Whh(h2)
__device__ float g_benc0[1024];
__device__ float g_benc1[1024];
__device__ float g_bdec0[1024];         // bih+bhh + d_Wih0@fc_b   (t>=1)
__device__ float g_bdec0t0[1024];       // bih+bhh                 (t==0, zero input)
__device__ float g_bdec1[1024];
__device__ float g_fcWT[256 * 128];     // fc_W transposed: [u][d]

__device__ float g_h1e[2][HB];
__device__ float g_h2e[2][HB];
__device__ float g_h1d[2][HB];
__device__ float g_zero[HB];
__device__ float g_hist[512ll * HB];    // decoder h2 history [t][b][u]  (128 MB)

__device__ unsigned g_barCnt = 0;
__device__ unsigned g_barGen = 0;

// ---- helpers ---------------------------------------------------------------
__device__ __forceinline__ float sigf(float v) { return 1.0f / (1.0f + __expf(-v)); }

__device__ __forceinline__ unsigned long long splat2(float v) {
    unsigned long long r;
    unsigned u = __float_as_uint(v);
    asm("mov.b64 %0, {%1, %1};" : "=l"(r) : "r"(u));
    return r;
}
__device__ __forceinline__ void ffma2(unsigned long long& d,
                                      unsigned long long a, unsigned long long b) {
    asm("fma.rn.f32x2 %0, %1, %2, %0;" : "+l"(d) : "l"(a), "l"(b));
}
__device__ __forceinline__ float2 unpack2(unsigned long long v) {
    float2 f;
    asm("mov.b64 {%0, %1}, %2;" : "=f"(f.x), "=f"(f.y) : "l"(v));
    return f;
}

__device__ __forceinline__ void gridbar() {
    __syncthreads();
    if (threadIdx.x == 0) {
        unsigned gen = *(volatile unsigned*)&g_barGen;
        __threadfence();
        if (atomicAdd(&g_barCnt, 1u) == NB - 1) {
            atomicExch(&g_barCnt, 0u);
            __threadfence();
            atomicAdd(&g_barGen, 1u);
        } else {
            while (*(volatile unsigned*)&g_barGen == gen) { }
        }
        __threadfence();
    }
    __syncthreads();
}

#define CP16(dst_generic, src) do {                                         \
    unsigned _d = (unsigned)__cvta_generic_to_shared(dst_generic);          \
    asm volatile("cp.async.cg.shared.global [%0], [%1], 16;\n"              \
                 :: "r"(_d), "l"(src));                                     \
} while (0)

// smem layout (dynamic): As[2][32][68] then Bs[2][64][64]
#define AS_STRIDE 68
#define AS_BUF   2176       // 32*68
#define BS_BUF   4096       // 64*64
#define SMEM_FLOATS (2*AS_BUF + 2*BS_BUF)   // 12544 floats = 50176 B

// stage one 64-wide k tile of A (activations) and B (weights) into smem
__device__ __forceinline__ void stage_tile(
    int tile, int buf,
    const float* __restrict__ a0, long sa0, int k0len,
    const float* __restrict__ a1, long sa1,
    const float* __restrict__ W,
    float* As, float* Bs, int rb, int gb, int tid)
{
    int kbase = tile << 6;
    const float* sA; long st; int kl;
    if (kbase < k0len) { sA = a0; st = sa0; kl = kbase; }
    else               { sA = a1; st = sa1; kl = kbase - k0len; }
#pragma unroll
    for (int j = 0; j < 4; j++) {
        int idx = tid + j * NT;              // 0..511
        int r = idx >> 4, kq = idx & 15;
        const float* src = sA + (long)(rb * 32 + r) * st + kl + kq * 4;
        CP16(As + buf * AS_BUF + r * AS_STRIDE + kq * 4, src);
    }
#pragma unroll
    for (int j = 0; j < 8; j++) {
        int idx = tid + j * NT;              // 0..1023
        int kk = idx >> 4, gq = idx & 15;
        const float* src = W + (long)(kbase + kk) * 1024 + gb * 64 + gq * 4;
        CP16(Bs + buf * BS_BUF + kk * 64 + gq * 4, src);
    }
    asm volatile("cp.async.commit_group;\n");
}

// one LSTM cell phase: gates[256x1024] = A[256xK] @ W[Kx1024] + b ; nonlinearity
// thread tile: 2 rows x 8 gates (gate-quads tx and tx+8)
__device__ __forceinline__ void lstm_phase(
    const float* __restrict__ a0, long sa0, int k0len,
    const float* __restrict__ a1, long sa1,
    const float* __restrict__ W, const float* __restrict__ bias,
    int K, float* __restrict__ hout, float* c,
    float* As, float* Bs, int rb, int gb, int tx, int ty, int tid)
{
    unsigned long long acc00if = 0, acc00go = 0, acc01if = 0, acc01go = 0;
    unsigned long long acc10if = 0, acc10go = 0, acc11if = 0, acc11go = 0;
    int nt = K >> 6;

    stage_tile(0, 0, a0, sa0, k0len, a1, sa1, W, As, Bs, rb, gb, tid);

    for (int tl = 0; tl < nt; tl++) {
        if (tl + 1 < nt) {
            stage_tile(tl + 1, (tl + 1) & 1, a0, sa0, k0len, a1, sa1, W, As, Bs, rb, gb, tid);
            asm volatile("cp.async.wait_group 1;\n");
        } else {
            asm volatile("cp.async.wait_group 0;\n");
        }
        __syncthreads();

        const float* Asb = As + (tl & 1) * AS_BUF + (ty * 2) * AS_STRIDE;
        const float* Bsb = Bs + (tl & 1) * BS_BUF + tx * 4;
#pragma unroll 2
        for (int k = 0; k < 64; k += 4) {
            float4 av0 = *(const float4*)(Asb + k);
            float4 av1 = *(const float4*)(Asb + AS_STRIDE + k);
#define STEP(KK, AC)                                                        \
            {                                                               \
                const float* bp = Bsb + (k + KK) * 64;                      \
                ulonglong2 bl = *(const ulonglong2*)bp;                     \
                ulonglong2 bh = *(const ulonglong2*)(bp + 32);              \
                unsigned long long s0 = splat2(av0.AC);                     \
                unsigned long long s1 = splat2(av1.AC);                     \
                ffma2(acc00if, s0, bl.x); ffma2(acc00go, s0, bl.y);         \
                ffma2(acc01if, s0, bh.x); ffma2(acc01go, s0, bh.y);         \
                ffma2(acc10if, s1, bl.x); ffma2(acc10go, s1, bl.y);         \
                ffma2(acc11if, s1, bh.x); ffma2(acc11go, s1, bh.y);         \
            }
            STEP(0, x) STEP(1, y) STEP(2, z) STEP(3, w)
#undef STEP
        }
        __syncthreads();
    }

    // epilogue: each acc pair = (i,f) / (g,o) of one unit; LSTM nonlinearity
    const float* bq = bias + gb * 64 + tx * 4;
    float4 bv0 = *(const float4*)bq;          // quad tx
    float4 bv1 = *(const float4*)(bq + 32);   // quad tx+8
    int row0 = rb * 32 + ty * 2;
    int col0 = gb * 16 + tx;
#define CELL(AIF, AGO, BV, CI, ROW, COL)                                \
    {                                                                   \
        float2 pif = unpack2(AIF);                                      \
        float2 pgo = unpack2(AGO);                                      \
        float iv = pif.x + BV.x, fv = pif.y + BV.y;                     \
        float gv = pgo.x + BV.z, ov = pgo.y + BV.w;                     \
        float cn = sigf(fv) * c[CI] + sigf(iv) * tanhf(gv);             \
        c[CI] = cn;                                                     \
        hout[(ROW) * 256 + (COL)] = sigf(ov) * tanhf(cn);               \
    }
    CELL(acc00if, acc00go, bv0, 0, row0,     col0)
    CELL(acc01if, acc01go, bv1, 1, row0,     col0 + 8)
    CELL(acc10if, acc10go, bv0, 2, row0 + 1, col0)
    CELL(acc11if, acc11go, bv1, 3, row0 + 1, col0 + 8)
#undef CELL
}

// ---- persistent kernel ------------------------------------------------------
__global__ void __launch_bounds__(NT, 1) lstm_persistent(const float* __restrict__ x)
{
    extern __shared__ float sm[];
    float* As = sm;
    float* Bs = sm + 2 * AS_BUF;

    int tid = threadIdx.x, bid = blockIdx.x;
    int rb = bid & 7;        // row block  (8 x 32 rows)
    int gb = bid >> 3;       // gate block (16 x 64 gate cols)
    int tx = tid & 7;        // gate-quad pair index (quads tx, tx+8)
    int ty = tid >> 3;       // row pair index (rows 2ty, 2ty+1)

    // zero-init state buffers
    for (int i = bid * NT + tid; i < HB; i += NB * NT) {
        g_h1e[0][i] = 0.f; g_h1e[1][i] = 0.f;
        g_h2e[0][i] = 0.f; g_h2e[1][i] = 0.f;
        g_h1d[0][i] = 0.f; g_h1d[1][i] = 0.f;
        g_zero[i]   = 0.f;
    }
    gridbar();

    float c1e[4] = {0.f,0.f,0.f,0.f};
    float c2e[4] = {0.f,0.f,0.f,0.f};

    // ---------------- encoder ----------------
    for (int t = 0; t < 512; t++) {
        int cur = t & 1, prv = cur ^ 1;
        lstm_phase(x + (long)t * 128, 65536L, 128, g_h1e[prv], 256L,
                   g_Wenc0, g_benc0, 384, g_h1e[cur], c1e,
                   As, Bs, rb, gb, tx, ty, tid);
        gridbar();
        lstm_phase(g_h1e[cur], 256L, 256, g_h2e[prv], 256L,
                   g_Wenc1, g_benc1, 512, g_h2e[cur], c2e,
                   As, Bs, rb, gb, tx, ty, tid);
        gridbar();
    }

    // decoder initial states = encoder final states (same thread->cell mapping)
    float c1d[4], c2d[4];
#pragma unroll
    for (int rr = 0; rr < 4; rr++) { c1d[rr] = c1e[rr]; c2d[rr] = c2e[rr]; }

    // ---------------- decoder ----------------
    for (int t = 0; t < 512; t++) {
        int cur = t & 1, prv = cur ^ 1;
        const float* in0 = (t == 0) ? g_zero    : (g_hist + (long)(t - 1) * HB);
        const float* h1p = (t == 0) ? g_h1e[1]  : g_h1d[prv];
        const float* h2p = (t == 0) ? g_h2e[1]  : (g_hist + (long)(t - 1) * HB);
        const float* b0  = (t == 0) ? g_bdec0t0 : g_bdec0;

        lstm_phase(in0, 256L, 256, h1p, 256L,
                   g_Wdec0, b0, 512, g_h1d[cur], c1d,
                   As, Bs, rb, gb, tx, ty, tid);
        gridbar();
        lstm_phase(g_h1d[cur], 256L, 256, h2p, 256L,
                   g_Wdec1, g_bdec1, 512, g_hist + (long)t * HB, c2d,
                   As, Bs, rb, gb, tx, ty, tid);
        gridbar();
    }
}

// ---- prep kernels -----------------------------------------------------------
// permute weights into [k][gatecol] with gatecol = 4*unit + gate  (gate: i,f,g,o)
__global__ void prep_std(const float* __restrict__ Wih, const float* __restrict__ Whh,
                         const float* __restrict__ bih, const float* __restrict__ bhh,
                         int inDim, int which)
{
    float* Wd = (which == 0) ? g_Wenc0 : (which == 1) ? g_Wenc1 : g_Wdec1;
    float* bd = (which == 0) ? g_benc0 : (which == 1) ? g_benc1 : g_bdec1;
    int K = inDim + 256;
    int idx = blockIdx.x * 256 + threadIdx.x;
    if (idx < K * 1024) {
        int k = idx >> 10, ccol = idx & 1023;
        int u = ccol >> 2, j = ccol & 3;
        int sr = j * 256 + u;
        Wd[idx] = (k < inDim) ? Wih[sr * inDim + k] : Whh[sr * 256 + (k - inDim)];
    }
    if (idx < 1024) {
        int u = idx >> 2, j = idx & 3;
        int sr = j * 256 + u;
        bd[idx] = bih[sr] + bhh[sr];
    }
}

// decoder layer 0: fold fc feedback:  W' = d_Wih0 @ fc_W,  b' += d_Wih0 @ fc_b
__global__ void prep_dec0(const float* __restrict__ Wih, const float* __restrict__ Whh,
                          const float* __restrict__ bih, const float* __restrict__ bhh,
                          const float* __restrict__ fcW, const float* __restrict__ fcb)
{
    int idx = blockIdx.x * 256 + threadIdx.x;
    if (idx < 512 * 1024) {
        int k = idx >> 10, ccol = idx & 1023;
        int u = ccol >> 2, j = ccol & 3;
        int sr = j * 256 + u;
        float v;
        if (k < 256) {
            float s = 0.f;
            for (int jj = 0; jj < 128; jj++)
                s += Wih[sr * 128 + jj] * fcW[jj * 256 + k];
            v = s;
        } else {
            v = Whh[sr * 256 + (k - 256)];
        }
        g_Wdec0[idx] = v;
    }
    if (idx < 1024) {
        int u = idx >> 2, j = idx & 3;
        int sr = j * 256 + u;
        float bb = bih[sr] + bhh[sr];
        g_bdec0t0[idx] = bb;
        float s = 0.f;
        for (int jj = 0; jj < 128; jj++)
            s += Wih[sr * 128 + jj] * fcb[jj];
        g_bdec0[idx] = bb + s;
    }
}

__global__ void prep_fcwt(const float* __restrict__ fcW)
{
    int idx = blockIdx.x * 256 + threadIdx.x;    // 32768
    if (idx < 256 * 128) {
        int u = idx >> 7, d = idx & 127;
        g_fcWT[idx] = fcW[d * 256 + u];
    }
}

// ---- final output GEMM:  y[b][t][:] = hist[t][b][:] @ fc_W^T + fc_b ---------
__global__ void __launch_bounds__(256) out_gemm(const float* __restrict__ fcb,
                                                float* __restrict__ out)
{
    __shared__ float As[32 * 64];
    __shared__ float Bs[64 * 128];
    int tid = threadIdx.x;
    long rowBase = (long)blockIdx.x * 32;   // global row g = t*256 + b
    int dx = tid & 31;   // d quad
    int ry = tid >> 5;   // 8 -> 4 rows each
    float acc[4][4] = {};
    for (int kb = 0; kb < 256; kb += 64) {
        __syncthreads();
#pragma unroll
        for (int j = 0; j < 2; j++) {
            int idx = tid + j * 256;  int r = idx >> 4, kq = idx & 15;
            *(float4*)&As[r * 64 + kq * 4] =
                *(const float4*)&g_hist[(rowBase + r) * 256 + kb + kq * 4];
        }
#pragma unroll
        for (int j = 0; j < 8; j++) {
            int idx = tid + j * 256;  int k = idx >> 5, dq = idx & 31;
            *(float4*)&Bs[k * 128 + dq * 4] =
                *(const float4*)&g_fcWT[(kb + k) * 128 + dq * 4];
        }
        __syncthreads();
#pragma unroll 4
        for (int k = 0; k < 64; k++) {
            float4 b = *(const float4*)&Bs[k * 128 + dx * 4];
#pragma unroll
            for (int rr = 0; rr < 4; rr++) {
                float a = As[(ry * 4 + rr) * 64 + k];
                acc[rr][0] += a * b.x; acc[rr][1] += a * b.y;
                acc[rr][2] += a * b.z; acc[rr][3] += a * b.w;
            }
        }
    }
    float4 bb = *(const float4*)&fcb[dx * 4];
#pragma unroll
    for (int rr = 0; rr < 4; rr++) {
        long g = rowBase + ry * 4 + rr;
        long b = g & 255, t = g >> 8;
        float4 v = make_float4(acc[rr][0] + bb.x, acc[rr][1] + bb.y,
                               acc[rr][2] + bb.z, acc[rr][3] + bb.w);
        *(float4*)&out[(b * 512 + t) * 128 + dx * 4] = v;
    }
}

// ---- launch -----------------------------------------------------------------
extern "C" void kernel_launch(void* const* d_in, const int* in_sizes, int n_in,
                              void* d_out, int out_size)
{
    const float* x      = (const float*)d_in[0];
    const float* eWih0  = (const float*)d_in[1];
    const float* eWhh0  = (const float*)d_in[2];
    const float* ebih0  = (const float*)d_in[3];
    const float* ebhh0  = (const float*)d_in[4];
    const float* eWih1  = (const float*)d_in[5];
    const float* eWhh1  = (const float*)d_in[6];
    const float* ebih1  = (const float*)d_in[7];
    const float* ebhh1  = (const float*)d_in[8];
    const float* dWih0  = (const float*)d_in[9];
    const float* dWhh0  = (const float*)d_in[10];
    const float* dbih0  = (const float*)d_in[11];
    const float* dbhh0  = (const float*)d_in[12];
    const float* dWih1  = (const float*)d_in[13];
    const float* dWhh1  = (const float*)d_in[14];
    const float* dbih1  = (const float*)d_in[15];
    const float* dbhh1  = (const float*)d_in[16];
    const float* fcW    = (const float*)d_in[17];
    const float* fcb    = (const float*)d_in[18];
    float* out = (float*)d_out;

    prep_std<<<1536, 256>>>(eWih0, eWhh0, ebih0, ebhh0, 128, 0);
    prep_std<<<2048, 256>>>(eWih1, eWhh1, ebih1, ebhh1, 256, 1);
    prep_std<<<2048, 256>>>(dWih1, dWhh1, dbih1, dbhh1, 256, 2);
    prep_dec0<<<2048, 256>>>(dWih0, dWhh0, dbih0, dbhh0, fcW, fcb);
    prep_fcwt<<<128, 256>>>(fcW);

    cudaFuncSetAttribute(lstm_persistent,
                         cudaFuncAttributeMaxDynamicSharedMemorySize,
                         SMEM_FLOATS * 4);
    lstm_persistent<<<NB, NT, SMEM_FLOATS * 4>>>(x);

    out_gemm<<<4096, 256>>>(fcb, out);
}

// round 15
// speedup vs baseline: 1.8618x; 1.8589x over previous
#include <cuda_runtime.h>
#include <cuda_bf16.h>
#include <cstdint>

// ============================================================================
// LSTM autoencoder  B=256 T=512 D=128 H=256
// Persistent kernel, 128 CTAs x 256 thr, bf16 split-precision mma.sync (HMMA).
// ============================================================================

#define NB 128
#define NT 256
#define HB 65536   // 256*256 elements per h buffer

// ---- device-global scratch ---------------------------------------------------
__device__ __nv_bfloat16 g_We0[2][1024 * 384];   // [half][gatecol][k]
__device__ __nv_bfloat16 g_We1[2][1024 * 512];
__device__ __nv_bfloat16 g_Wd0[2][1024 * 512];   // k<256: d_Wih0@fc_W, else Whh
__device__ __nv_bfloat16 g_Wd1[2][1024 * 512];
__device__ float g_be0[1024], g_be1[1024], g_bd0[1024], g_bd0t0[1024], g_bd1[1024];
__device__ __nv_bfloat16 g_x[2][512 * 256 * 128];  // [half][(t*256+b)*128+d]
__device__ __nv_bfloat16 g_hb[9][2][HB];           // 0/1 h1e, 2/3 h2e, 4/5 h1d, 6/7 h2d, 8 zero
__device__ float g_fcWT[256 * 128];
__device__ float g_hist[512ll * HB];
__device__ unsigned g_barCnt = 0, g_barGen = 0;

__device__ __forceinline__ float sigf(float v) { return 1.0f / (1.0f + __expf(-v)); }
__device__ __forceinline__ uint32_t smem_u32(const void* p) {
    uint32_t a;
    asm("{ .reg .u64 t; cvta.to.shared.u64 t, %1; cvt.u32.u64 %0, t; }" : "=r"(a) : "l"(p));
    return a;
}
__device__ __forceinline__ void gridbar() {
    __syncthreads();
    if (threadIdx.x == 0) {
        unsigned gen = *(volatile unsigned*)&g_barGen;
        __threadfence();
        if (atomicAdd(&g_barCnt, 1u) == NB - 1) {
            atomicExch(&g_barCnt, 0u);
            __threadfence();
            atomicAdd(&g_barGen, 1u);
        } else {
            while (*(volatile unsigned*)&g_barGen == gen) { }
        }
        __threadfence();
    }
    __syncthreads();
}

#define CP16(dst, src) do { uint32_t _d = (dst);                              \
    asm volatile("cp.async.cg.shared.global [%0], [%1], 16;" :: "r"(_d), "l"(src)); } while (0)

#define LDSM4(R, ADDR) asm volatile(                                          \
    "ldmatrix.sync.aligned.m8n8.x4.shared.b16 {%0,%1,%2,%3}, [%4];"           \
    : "=r"((R)[0]), "=r"((R)[1]), "=r"((R)[2]), "=r"((R)[3]) : "r"(ADDR))

#define MMA(AC, A, B0, B1) asm volatile(                                      \
    "mma.sync.aligned.m16n8k16.row.col.f32.bf16.bf16.f32 "                    \
    "{%0,%1,%2,%3},{%4,%5,%6,%7},{%8,%9},{%0,%1,%2,%3};"                      \
    : "+f"((AC)[0]), "+f"((AC)[1]), "+f"((AC)[2]), "+f"((AC)[3])              \
    : "r"((A)[0]), "r"((A)[1]), "r"((A)[2]), "r"((A)[3]), "r"(B0), "r"(B1))

// smem: double buffer; per buf: Ahi[32*144] Alo Bhi[64*144] Blo = 27648 B
#define ABUF 4608
#define BBUF 9216
#define BUFB (2*ABUF + 2*BBUF)          // 27648
#define SMEM_BYTES (2 * BUFB)           // 55296

// stage one 64-wide k chunk: A rows 32 (hi+lo), B gate-rows 64 (hi+lo)
__device__ __forceinline__ void stage_chunk(int ch, uint32_t smb,
    const __nv_bfloat16* a0h, const __nv_bfloat16* a0l, int s0, int k0,
    const __nv_bfloat16* a1h, const __nv_bfloat16* a1l,
    const __nv_bfloat16* Wh, const __nv_bfloat16* Wl, int K,
    int rb, int gb, int tid)
{
    int kb = ch << 6;
    const __nv_bfloat16 *ah, *al; int st, kl;
    if (kb < k0) { ah = a0h; al = a0l; st = s0;  kl = kb; }
    else         { ah = a1h; al = a1l; st = 256; kl = kb - k0; }
    uint32_t base = smb + (ch & 1) * BUFB;
#pragma unroll
    for (int j = 0; j < 2; j++) {                 // A: 512 x 16B (hi 256 + lo 256)
        int idx = tid + j * NT;
        int hf = idx >> 8, r = (idx >> 3) & 31, p = idx & 7;
        const __nv_bfloat16* src = (hf ? al : ah) + (long)(rb * 32 + r) * st + kl + p * 8;
        CP16(base + hf * ABUF + r * 144 + p * 16, src);
    }
#pragma unroll
    for (int j = 0; j < 4; j++) {                 // B: 1024 x 16B (hi 512 + lo 512)
        int idx = tid + j * NT;
        int hf = idx >> 9, n = (idx >> 3) & 63, p = idx & 7;
        const __nv_bfloat16* src = (hf ? Wl : Wh) + (long)(gb * 64 + n) * K + kb + p * 8;
        CP16(base + 2 * ABUF + hf * BBUF + n * 144 + p * 16, src);
    }
    asm volatile("cp.async.commit_group;" ::: "memory");
}

// one LSTM phase: gates[256x1024] = A[256xK]@W^T + b ; nonlinearity
__device__ __forceinline__ void lstm_phase(
    const __nv_bfloat16* a0h, const __nv_bfloat16* a0l, int s0, int k0,
    const __nv_bfloat16* a1h, const __nv_bfloat16* a1l,
    const __nv_bfloat16* Wh, const __nv_bfloat16* Wl, int K, const float* bias,
    __nv_bfloat16* ohi, __nv_bfloat16* olo, float* of32, float* c,
    uint32_t smb, int rb, int gb, int tid)
{
    int l = tid & 31, w = tid >> 5;
    int rh = w & 1, wc = w >> 1;
    // per-lane ldmatrix offsets (bytes)
    uint32_t laneA = (uint32_t)((rh * 16 + (l & 15)) * 144 + ((l >> 4) & 1) * 16);
    uint32_t laneB = (uint32_t)((wc * 16 + ((l >> 4) & 1) * 8 + (l & 7)) * 144
                                + ((l >> 3) & 1) * 16);
    float acc0[4] = {0.f, 0.f, 0.f, 0.f};
    float acc1[4] = {0.f, 0.f, 0.f, 0.f};
    int nt = K >> 6;

    stage_chunk(0, smb, a0h, a0l, s0, k0, a1h, a1l, Wh, Wl, K, rb, gb, tid);

    for (int tl = 0; tl < nt; tl++) {
        if (tl + 1 < nt) {
            stage_chunk(tl + 1, smb, a0h, a0l, s0, k0, a1h, a1l, Wh, Wl, K, rb, gb, tid);
            asm volatile("cp.async.wait_group 1;" ::: "memory");
        } else {
            asm volatile("cp.async.wait_group 0;" ::: "memory");
        }
        __syncthreads();

        uint32_t base = smb + (tl & 1) * BUFB;
        uint32_t aH = base + laneA;
        uint32_t aL = aH + ABUF;
        uint32_t bH = base + 2 * ABUF + laneB;
        uint32_t bL = bH + BBUF;
#pragma unroll
        for (int ks = 0; ks < 4; ks++) {
            uint32_t ra[4], la[4], rbh[4], rbl[4];
            LDSM4(ra,  aH + ks * 32);
            LDSM4(la,  aL + ks * 32);
            LDSM4(rbh, bH + ks * 32);
            LDSM4(rbl, bL + ks * 32);
            MMA(acc0, ra, rbh[0], rbh[1]);
            MMA(acc0, la, rbh[0], rbh[1]);
            MMA(acc0, ra, rbl[0], rbl[1]);
            MMA(acc1, ra, rbh[2], rbh[3]);
            MMA(acc1, la, rbh[2], rbh[3]);
            MMA(acc1, ra, rbl[2], rbl[3]);
        }
        __syncthreads();
    }

    // epilogue: pair (i,f)/(g,o) lanes via shfl, LSTM cell, write h
    int g = l >> 2, t4 = l & 3;
    int odd = t4 & 1;
#pragma unroll
    for (int n2 = 0; n2 < 2; n2++) {
        float* A = n2 ? acc1 : acc0;
        float s0v = odd ? A[0] : A[2];
        float s1v = odd ? A[1] : A[3];
        float r0 = __shfl_xor_sync(0xFFFFFFFFu, s0v, 1);
        float r1 = __shfl_xor_sync(0xFFFFFFFFu, s1v, 1);
        float iv, fv, gv, ov; int rowC;
        if (!odd) { iv = A[0]; fv = A[1]; gv = r0;   ov = r1;   rowC = rh * 16 + g; }
        else      { iv = r0;   fv = r1;   gv = A[2]; ov = A[3]; rowC = rh * 16 + g + 8; }
        int unit = wc * 4 + n2 * 2 + (t4 >> 1);
        float4 bv = *(const float4*)&bias[gb * 64 + unit * 4];
        iv += bv.x; fv += bv.y; gv += bv.z; ov += bv.w;
        float cn = sigf(fv) * c[n2] + sigf(iv) * tanhf(gv);
        c[n2] = cn;
        float h = sigf(ov) * tanhf(cn);
        int row = rb * 32 + rowC, uG = gb * 16 + unit;
        __nv_bfloat16 hh = __float2bfloat16(h);
        ohi[row * 256 + uG] = hh;
        olo[row * 256 + uG] = __float2bfloat16(h - __bfloat162float(hh));
        if (of32) of32[row * 256 + uG] = h;
    }
}

// ---- persistent kernel --------------------------------------------------------
__global__ void __launch_bounds__(NT, 1) lstm_mma()
{
    extern __shared__ char sm[];
    uint32_t smb = smem_u32(sm);
    int tid = threadIdx.x, bid = blockIdx.x;
    int rb = bid & 7;        // 8 row blocks of 32
    int gb = bid >> 3;       // 16 gate blocks of 64

    float c1[2] = {0.f, 0.f}, c2[2] = {0.f, 0.f};

    for (int t = 0; t < 512; t++) {
        int cur = t & 1, prv = cur ^ 1;
        lstm_phase(g_x[0] + (long)t * 32768, g_x[1] + (long)t * 32768, 128, 128,
                   g_hb[0 + prv][0], g_hb[0 + prv][1], g_We0[0], g_We0[1], 384, g_be0,
                   g_hb[0 + cur][0], g_hb[0 + cur][1], nullptr, c1,
                   smb, rb, gb, tid);
        gridbar();
        lstm_phase(g_hb[0 + cur][0], g_hb[0 + cur][1], 256, 256,
                   g_hb[2 + prv][0], g_hb[2 + prv][1], g_We1[0], g_We1[1], 512, g_be1,
                   g_hb[2 + cur][0], g_hb[2 + cur][1], nullptr, c2,
                   smb, rb, gb, tid);
        gridbar();
    }
    for (int t = 0; t < 512; t++) {
        int cur = t & 1, prv = cur ^ 1;
        const __nv_bfloat16* i0h = (t == 0) ? g_hb[8][0] : g_hb[6 + prv][0];
        const __nv_bfloat16* i0l = (t == 0) ? g_hb[8][1] : g_hb[6 + prv][1];
        const __nv_bfloat16* h1h = (t == 0) ? g_hb[1][0] : g_hb[4 + prv][0];
        const __nv_bfloat16* h1l = (t == 0) ? g_hb[1][1] : g_hb[4 + prv][1];
        const __nv_bfloat16* h2h = (t == 0) ? g_hb[3][0] : g_hb[6 + prv][0];
        const __nv_bfloat16* h2l = (t == 0) ? g_hb[3][1] : g_hb[6 + prv][1];
        const float* b0 = (t == 0) ? g_bd0t0 : g_bd0;
        lstm_phase(i0h, i0l, 256, 256, h1h, h1l, g_Wd0[0], g_Wd0[1], 512, b0,
                   g_hb[4 + cur][0], g_hb[4 + cur][1], nullptr, c1,
                   smb, rb, gb, tid);
        gridbar();
        lstm_phase(g_hb[4 + cur][0], g_hb[4 + cur][1], 256, 256, h2h, h2l,
                   g_Wd1[0], g_Wd1[1], 512, g_bd1,
                   g_hb[6 + cur][0], g_hb[6 + cur][1], g_hist + (long)t * HB, c2,
                   smb, rb, gb, tid);
        gridbar();
    }
}

// ---- prep ----------------------------------------------------------------
__device__ __forceinline__ void splitst(__nv_bfloat16* hi, __nv_bfloat16* lo, long i, float v) {
    __nv_bfloat16 h = __float2bfloat16(v);
    hi[i] = h; lo[i] = __float2bfloat16(v - __bfloat162float(h));
}
// weights -> [gatecol][k] bf16 hi/lo, gatecol = 4*unit + gate(i,f,g,o)
__global__ void prep_w(const float* Wih, const float* Whh, const float* bih,
                       const float* bhh, int inDim, int which)
{
    __nv_bfloat16* hi = (which == 0) ? g_We0[0] : (which == 1) ? g_We1[0] : g_Wd1[0];
    __nv_bfloat16* lo = (which == 0) ? g_We0[1] : (which == 1) ? g_We1[1] : g_Wd1[1];
    float* bd = (which == 0) ? g_be0 : (which == 1) ? g_be1 : g_bd1;
    int K = inDim + 256;
    long idx = (long)blockIdx.x * 256 + threadIdx.x;
    if (idx < (long)K * 1024) {
        int g = (int)(idx / K), k = (int)(idx % K);
        int u = g >> 2, j = g & 3, sr = j * 256 + u;
        float v = (k < inDim) ? Wih[(long)sr * inDim + k] : Whh[(long)sr * 256 + (k - inDim)];
        splitst(hi, lo, idx, v);
    }
    if (idx < 1024) {
        int u = (int)idx >> 2, j = (int)idx & 3;
        bd[idx] = bih[j * 256 + u] + bhh[j * 256 + u];
    }
}
__global__ void prep_d0(const float* Wih, const float* Whh, const float* bih,
                        const float* bhh, const float* fcW, const float* fcb)
{
    long idx = (long)blockIdx.x * 256 + threadIdx.x;
    if (idx < 512l * 1024) {
        int g = (int)(idx >> 9), k = (int)(idx & 511);
        int u = g >> 2, j = g & 3, sr = j * 256 + u;
        float v;
        if (k < 256) {
            float s = 0.f;
            for (int d = 0; d < 128; d++) s += Wih[sr * 128 + d] * fcW[d * 256 + k];
            v = s;
        } else v = Whh[(long)sr * 256 + (k - 256)];
        splitst(g_Wd0[0], g_Wd0[1], idx, v);
    }
    if (idx < 1024) {
        int u = (int)idx >> 2, j = (int)idx & 3, sr = j * 256 + u;
        float bb = bih[sr] + bhh[sr];
        g_bd0t0[idx] = bb;
        float s = 0.f;
        for (int d = 0; d < 128; d++) s += Wih[sr * 128 + d] * fcb[d];
        g_bd0[idx] = bb + s;
    }
}
__global__ void prep_x(const float* x)
{
    long idx = (long)blockIdx.x * 256 + threadIdx.x;
    if (idx < 512l * 256 * 128) {
        long t = idx >> 15, b = (idx >> 7) & 255, d = idx & 127;
        splitst(g_x[0], g_x[1], idx, x[(b * 512 + t) * 128 + d]);
    }
}
__global__ void prep_zero()
{
    long idx = (long)blockIdx.x * 256 + threadIdx.x;
    uint32_t* p = (uint32_t*)&g_hb[0][0][0];
    if (idx < 9l * 2 * HB / 2) p[idx] = 0u;
}
__global__ void prep_fcwt(const float* fcW)
{
    int idx = blockIdx.x * 256 + threadIdx.x;
    if (idx < 256 * 128) g_fcWT[idx] = fcW[(idx & 127) * 256 + (idx >> 7)];
}

// ---- final fc GEMM ---------------------------------------------------------
__global__ void __launch_bounds__(256) out_gemm(const float* __restrict__ fcb,
                                                float* __restrict__ out)
{
    __shared__ float As[32 * 64];
    __shared__ float Bs[64 * 128];
    int tid = threadIdx.x;
    long rowBase = (long)blockIdx.x * 32;
    int dx = tid & 31, ry = tid >> 5;
    float acc[4][4] = {};
    for (int kb = 0; kb < 256; kb += 64) {
        __syncthreads();
#pragma unroll
        for (int j = 0; j < 2; j++) {
            int idx = tid + j * 256; int r = idx >> 4, kq = idx & 15;
            *(float4*)&As[r * 64 + kq * 4] =
                *(const float4*)&g_hist[(rowBase + r) * 256 + kb + kq * 4];
        }
#pragma unroll
        for (int j = 0; j < 8; j++) {
            int idx = tid + j * 256; int k = idx >> 5, dq = idx & 31;
            *(float4*)&Bs[k * 128 + dq * 4] =
                *(const float4*)&g_fcWT[(kb + k) * 128 + dq * 4];
        }
        __syncthreads();
#pragma unroll 4
        for (int k = 0; k < 64; k++) {
            float4 b = *(const float4*)&Bs[k * 128 + dx * 4];
#pragma unroll
            for (int rr = 0; rr < 4; rr++) {
                float a = As[(ry * 4 + rr) * 64 + k];
                acc[rr][0] += a * b.x; acc[rr][1] += a * b.y;
                acc[rr][2] += a * b.z; acc[rr][3] += a * b.w;
            }
        }
    }
    float4 bb = *(const float4*)&fcb[dx * 4];
#pragma unroll
    for (int rr = 0; rr < 4; rr++) {
        long g = rowBase + ry * 4 + rr;
        long b = g & 255, t = g >> 8;
        *(float4*)&out[(b * 512 + t) * 128 + dx * 4] =
            make_float4(acc[rr][0] + bb.x, acc[rr][1] + bb.y,
                        acc[rr][2] + bb.z, acc[rr][3] + bb.w);
    }
}

extern "C" void kernel_launch(void* const* d_in, const int* in_sizes, int n_in,
                              void* d_out, int out_size)
{
    const float* x     = (const float*)d_in[0];
    const float* eWih0 = (const float*)d_in[1],  *eWhh0 = (const float*)d_in[2];
    const float* ebih0 = (const float*)d_in[3],  *ebhh0 = (const float*)d_in[4];
    const float* eWih1 = (const float*)d_in[5],  *eWhh1 = (const float*)d_in[6];
    const float* ebih1 = (const float*)d_in[7],  *ebhh1 = (const float*)d_in[8];
    const float* dWih0 = (const float*)d_in[9],  *dWhh0 = (const float*)d_in[10];
    const float* dbih0 = (const float*)d_in[11], *dbhh0 = (const float*)d_in[12];
    const float* dWih1 = (const float*)d_in[13], *dWhh1 = (const float*)d_in[14];
    const float* dbih1 = (const float*)d_in[15], *dbhh1 = (const float*)d_in[16];
    const float* fcW   = (const float*)d_in[17], *fcb   = (const float*)d_in[18];
    float* out = (float*)d_out;

    prep_w<<<1536, 256>>>(eWih0, eWhh0, ebih0, ebhh0, 128, 0);
    prep_w<<<2048, 256>>>(eWih1, eWhh1, ebih1, ebhh1, 256, 1);
    prep_w<<<2048, 256>>>(dWih1, dWhh1, dbih1, dbhh1, 256, 2);
    prep_d0<<<2048, 256>>>(dWih0, dWhh0, dbih0, dbhh0, fcW, fcb);
    prep_x<<<65536, 256>>>(x);
    prep_zero<<<2304, 256>>>();
    prep_fcwt<<<128, 256>>>(fcW);

    cudaFuncSetAttribute(lstm_mma, cudaFuncAttributeMaxDynamicSharedMemorySize, SMEM_BYTES);
    lstm_mma<<<NB, NT, SMEM_BYTES>>>();

    out_gemm<<<4096, 256>>>(fcb, out);
}

// round 16
// speedup vs baseline: 2.0910x; 1.1231x over previous
#include <cuda_runtime.h>
#include <cuda_bf16.h>
#include <cstdint>

// ============================================================================
// LSTM autoencoder  B=256 T=512 D=128 H=256
// Persistent kernel, 128 CTAs x 256 thr, bf16 split-precision mma.sync.
// Per-row-block dataflow sync (8 independent pipelines), cross-phase W prefetch.
// ============================================================================

#define NB 128
#define NT 256
#define HB 65536   // 256*256 elements per h buffer

// ---- device-global scratch -------------------------------------------------
__device__ __nv_bfloat16 g_We0[2][1024 * 384];   // [half][gatecol][k]
__device__ __nv_bfloat16 g_We1[2][1024 * 512];
__device__ __nv_bfloat16 g_Wd0[2][1024 * 512];   // k<256: d_Wih0@fc_W, else Whh
__device__ __nv_bfloat16 g_Wd1[2][1024 * 512];
__device__ float g_be0[1024], g_be1[1024], g_bd0[1024], g_bd0t0[1024], g_bd1[1024];
__device__ __nv_bfloat16 g_x[2][512 * 256 * 128];  // [half][(t*256+b)*128+d]
__device__ __nv_bfloat16 g_hb[9][2][HB];           // 0/1 h1e, 2/3 h2e, 4/5 h1d, 6/7 h2d, 8 zero
__device__ float g_fcWT[256 * 128];
__device__ float g_hist[512ll * HB];
__device__ unsigned g_cnt[8];                      // per-row-block phase counters

__device__ __forceinline__ float sigf(float v) { return 1.0f / (1.0f + __expf(-v)); }
__device__ __forceinline__ float tanhf_fast(float v) {
    return 1.0f - 2.0f / (1.0f + __expf(2.0f * v));
}
__device__ __forceinline__ uint32_t smem_u32(const void* p) {
    uint32_t a;
    asm("{ .reg .u64 t; cvta.to.shared.u64 t, %1; cvt.u32.u64 %0, t; }" : "=r"(a) : "l"(p));
    return a;
}

#define CP16(dst, src) do { uint32_t _d = (dst);                              \
    asm volatile("cp.async.cg.shared.global [%0], [%1], 16;" :: "r"(_d), "l"(src)); } while (0)
#define COMMIT() asm volatile("cp.async.commit_group;" ::: "memory")

#define LDSM4(R, ADDR) asm volatile(                                          \
    "ldmatrix.sync.aligned.m8n8.x4.shared.b16 {%0,%1,%2,%3}, [%4];"           \
    : "=r"((R)[0]), "=r"((R)[1]), "=r"((R)[2]), "=r"((R)[3]) : "r"(ADDR))

#define MMA(AC, A, B0, B1) asm volatile(                                      \
    "mma.sync.aligned.m16n8k16.row.col.f32.bf16.bf16.f32 "                    \
    "{%0,%1,%2,%3},{%4,%5,%6,%7},{%8,%9},{%0,%1,%2,%3};"                      \
    : "+f"((AC)[0]), "+f"((AC)[1]), "+f"((AC)[2]), "+f"((AC)[3])              \
    : "r"((A)[0]), "r"((A)[1]), "r"((A)[2]), "r"((A)[3]), "r"(B0), "r"(B1))

// smem: 3-buffer ring; per buf: Ahi[32*144] Alo | Bhi[64*144] Blo = 27648 B
#define ABUF 4608
#define BBUF 9216
#define BUFB (2*ABUF + 2*BBUF)          // 27648
#define SMEM_BYTES (3 * BUFB)           // 82944

// ---- staging (no commit inside; caller groups) -------------------------------
__device__ __forceinline__ void stage_A(int ch, uint32_t smb,
    const __nv_bfloat16* a0h, const __nv_bfloat16* a0l, int s0, int k0,
    const __nv_bfloat16* a1h, const __nv_bfloat16* a1l, int rb, int tid)
{
    int kb = ch << 6;
    const __nv_bfloat16 *ah, *al; int st, kl;
    if (kb < k0) { ah = a0h; al = a0l; st = s0;  kl = kb; }
    else         { ah = a1h; al = a1l; st = 256; kl = kb - k0; }
    uint32_t base = smb + (ch % 3) * BUFB;
#pragma unroll
    for (int j = 0; j < 2; j++) {                 // 512 x 16B (hi 256 + lo 256)
        int idx = tid + j * NT;
        int hf = idx >> 8, r = (idx >> 3) & 31, p = idx & 7;
        const __nv_bfloat16* src = (hf ? al : ah) + (long)(rb * 32 + r) * st + kl + p * 8;
        CP16(base + hf * ABUF + r * 144 + p * 16, src);
    }
}
__device__ __forceinline__ void stage_B(int ch, uint32_t smb,
    const __nv_bfloat16* Wh, const __nv_bfloat16* Wl, int K, int gb, int tid)
{
    int kb = ch << 6;
    uint32_t base = smb + (ch % 3) * BUFB + 2 * ABUF;
#pragma unroll
    for (int j = 0; j < 4; j++) {                 // 1024 x 16B (hi 512 + lo 512)
        int idx = tid + j * NT;
        int hf = idx >> 9, n = (idx >> 3) & 63, p = idx & 7;
        const __nv_bfloat16* src = (hf ? Wl : Wh) + (long)(gb * 64 + n) * K + kb + p * 8;
        CP16(base + hf * BBUF + n * 144 + p * 16, src);
    }
}

__device__ __forceinline__ void rb_wait(unsigned target, int rb, int tid)
{
    if (tid == 0) {
        while (*(volatile unsigned*)&g_cnt[rb] < target) { }
        __threadfence();
    }
    __syncthreads();
}

// ---- one LSTM phase -----------------------------------------------------------
__device__ __forceinline__ void run_phase(
    const __nv_bfloat16* a0h, const __nv_bfloat16* a0l, int s0, int k0,
    const __nv_bfloat16* a1h, const __nv_bfloat16* a1l,
    const __nv_bfloat16* Wh, const __nv_bfloat16* Wl, int K,
    const __nv_bfloat16* nWh, const __nv_bfloat16* nWl, int nK,
    const float* bias,
    __nv_bfloat16* ohi, __nv_bfloat16* olo, float* of32, float* c,
    uint32_t smb, uint32_t laneA, uint32_t laneB,
    int rb, int gb, int tid, bool first)
{
    int nt = K >> 6;
    if (first) {   // no carry-in prefetch: stage B of chunks 0,1 now
        stage_B(0, smb, Wh, Wl, K, gb, tid); COMMIT();
        stage_B(1, smb, Wh, Wl, K, gb, tid); COMMIT();
    }
    stage_A(0, smb, a0h, a0l, s0, k0, a1h, a1l, rb, tid); COMMIT();
    stage_A(1, smb, a0h, a0l, s0, k0, a1h, a1l, rb, tid); COMMIT();
    stage_A(2, smb, a0h, a0l, s0, k0, a1h, a1l, rb, tid);
    stage_B(2, smb, Wh, Wl, K, gb, tid); COMMIT();

    float acc0[4] = {0.f, 0.f, 0.f, 0.f};
    float acc1[4] = {0.f, 0.f, 0.f, 0.f};

    for (int i = 0; i < nt; i++) {
        int wg = nt - 1 - i;
        if (wg >= 2)      asm volatile("cp.async.wait_group 2;" ::: "memory");
        else if (wg == 1) asm volatile("cp.async.wait_group 1;" ::: "memory");
        else              asm volatile("cp.async.wait_group 0;" ::: "memory");
        __syncthreads();

        uint32_t base = smb + (i % 3) * BUFB;
        uint32_t aH = base + laneA;
        uint32_t aL = aH + ABUF;
        uint32_t bH = base + 2 * ABUF + laneB;
        uint32_t bL = bH + BBUF;
#pragma unroll
        for (int ks = 0; ks < 4; ks++) {
            uint32_t ra[4], la[4], rbh[4], rbl[4];
            LDSM4(ra,  aH + ks * 32);
            LDSM4(la,  aL + ks * 32);
            LDSM4(rbh, bH + ks * 32);
            LDSM4(rbl, bL + ks * 32);
            MMA(acc0, ra, rbh[0], rbh[1]);
            MMA(acc0, la, rbh[0], rbh[1]);
            MMA(acc0, ra, rbl[0], rbl[1]);
            MMA(acc1, ra, rbh[2], rbh[3]);
            MMA(acc1, la, rbh[2], rbh[3]);
            MMA(acc1, ra, rbl[2], rbl[3]);
        }
        __syncthreads();

        if (i + 3 < nt) {
            stage_A(i + 3, smb, a0h, a0l, s0, k0, a1h, a1l, rb, tid);
            stage_B(i + 3, smb, Wh, Wl, K, gb, tid);
            COMMIT();
        }
    }

    // tail: prefetch NEXT phase's weight chunks 0,1 (overlaps epilogue + sync)
    if (nWh) {
        stage_B(0, smb, nWh, nWl, nK, gb, tid); COMMIT();
        stage_B(1, smb, nWh, nWl, nK, gb, tid); COMMIT();
    }

    // epilogue: pair (i,f)/(g,o) lanes via shfl, LSTM cell, write h
    int l = tid & 31, w = tid >> 5;
    int rh = w & 1, wc = w >> 1;
    int g = l >> 2, t4 = l & 3;
    int odd = t4 & 1;
#pragma unroll
    for (int n2 = 0; n2 < 2; n2++) {
        float* A = n2 ? acc1 : acc0;
        float s0v = odd ? A[0] : A[2];
        float s1v = odd ? A[1] : A[3];
        float r0 = __shfl_xor_sync(0xFFFFFFFFu, s0v, 1);
        float r1 = __shfl_xor_sync(0xFFFFFFFFu, s1v, 1);
        float iv, fv, gv, ov; int rowC;
        if (!odd) { iv = A[0]; fv = A[1]; gv = r0;   ov = r1;   rowC = rh * 16 + g; }
        else      { iv = r0;   fv = r1;   gv = A[2]; ov = A[3]; rowC = rh * 16 + g + 8; }
        int unit = wc * 4 + n2 * 2 + (t4 >> 1);
        float4 bv = *(const float4*)&bias[gb * 64 + unit * 4];
        iv += bv.x; fv += bv.y; gv += bv.z; ov += bv.w;
        float cn = sigf(fv) * c[n2] + sigf(iv) * tanhf_fast(gv);
        c[n2] = cn;
        float h = sigf(ov) * tanhf_fast(cn);
        int row = rb * 32 + rowC, uG = gb * 16 + unit;
        __nv_bfloat16 hh = __float2bfloat16(h);
        ohi[row * 256 + uG] = hh;
        olo[row * 256 + uG] = __float2bfloat16(h - __bfloat162float(hh));
        if (of32) of32[row * 256 + uG] = h;
    }

    // release: make h visible, then signal this row-block
    __threadfence();
    __syncthreads();
    if (tid == 0) atomicAdd(&g_cnt[rb], 1u);
}

// ---- persistent kernel ----------------------------------------------------------
__global__ void __launch_bounds__(NT, 1) lstm_mma()
{
    extern __shared__ char sm[];
    uint32_t smb = smem_u32(sm);
    int tid = threadIdx.x, bid = blockIdx.x;
    int rb = bid & 7;        // 8 row blocks of 32
    int gb = bid >> 3;       // 16 gate blocks of 64
    int l = tid & 31, w = tid >> 5;
    int rh = w & 1, wc = w >> 1;
    uint32_t laneA = (uint32_t)((rh * 16 + (l & 15)) * 144 + ((l >> 4) & 1) * 16);
    uint32_t laneB = (uint32_t)((wc * 16 + ((l >> 4) & 1) * 8 + (l & 7)) * 144
                                + ((l >> 3) & 1) * 16);

    float c1[2] = {0.f, 0.f}, c2[2] = {0.f, 0.f};
    unsigned target = 0;
    bool first = true;

    for (int t = 0; t < 512; t++) {
        int cur = t & 1, prv = cur ^ 1;
        rb_wait(target, rb, tid);
        run_phase(g_x[0] + (long)t * 32768, g_x[1] + (long)t * 32768, 128, 128,
                  g_hb[prv][0], g_hb[prv][1],
                  g_We0[0], g_We0[1], 384,
                  g_We1[0], g_We1[1], 512,
                  g_be0, g_hb[cur][0], g_hb[cur][1], nullptr, c1,
                  smb, laneA, laneB, rb, gb, tid, first);
        first = false;
        target += 16;

        rb_wait(target, rb, tid);
        const __nv_bfloat16 *nwh, *nwl; int nk;
        if (t < 511) { nwh = g_We0[0]; nwl = g_We0[1]; nk = 384; }
        else         { nwh = g_Wd0[0]; nwl = g_Wd0[1]; nk = 512; }
        run_phase(g_hb[cur][0], g_hb[cur][1], 256, 256,
                  g_hb[2 + prv][0], g_hb[2 + prv][1],
                  g_We1[0], g_We1[1], 512,
                  nwh, nwl, nk,
                  g_be1, g_hb[2 + cur][0], g_hb[2 + cur][1], nullptr, c2,
                  smb, laneA, laneB, rb, gb, tid, false);
        target += 16;
    }

    for (int t = 0; t < 512; t++) {
        int cur = t & 1, prv = cur ^ 1;
        const __nv_bfloat16* i0h = (t == 0) ? g_hb[8][0] : g_hb[6 + prv][0];
        const __nv_bfloat16* i0l = (t == 0) ? g_hb[8][1] : g_hb[6 + prv][1];
        const __nv_bfloat16* h1h = (t == 0) ? g_hb[1][0] : g_hb[4 + prv][0];
        const __nv_bfloat16* h1l = (t == 0) ? g_hb[1][1] : g_hb[4 + prv][1];
        const __nv_bfloat16* h2h = (t == 0) ? g_hb[3][0] : g_hb[6 + prv][0];
        const __nv_bfloat16* h2l = (t == 0) ? g_hb[3][1] : g_hb[6 + prv][1];
        const float* b0 = (t == 0) ? g_bd0t0 : g_bd0;

        rb_wait(target, rb, tid);
        run_phase(i0h, i0l, 256, 256, h1h, h1l,
                  g_Wd0[0], g_Wd0[1], 512,
                  g_Wd1[0], g_Wd1[1], 512,
                  b0, g_hb[4 + cur][0], g_hb[4 + cur][1], nullptr, c1,
                  smb, laneA, laneB, rb, gb, tid, false);
        target += 16;

        rb_wait(target, rb, tid);
        const __nv_bfloat16 *nwh, *nwl; int nk = 512;
        if (t < 511) { nwh = g_Wd0[0]; nwl = g_Wd0[1]; }
        else         { nwh = nullptr;  nwl = nullptr; }
        run_phase(g_hb[4 + cur][0], g_hb[4 + cur][1], 256, 256, h2h, h2l,
                  g_Wd1[0], g_Wd1[1], 512,
                  nwh, nwl, nk,
                  g_bd1, g_hb[6 + cur][0], g_hb[6 + cur][1], g_hist + (long)t * HB, c2,
                  smb, laneA, laneB, rb, gb, tid, false);
        target += 16;
    }
}

// ---- prep -------------------------------------------------------------------
__device__ __forceinline__ void splitst(__nv_bfloat16* hi, __nv_bfloat16* lo, long i, float v) {
    __nv_bfloat16 h = __float2bfloat16(v);
    hi[i] = h; lo[i] = __float2bfloat16(v - __bfloat162float(h));
}
__global__ void prep_w(const float* Wih, const float* Whh, const float* bih,
                       const float* bhh, int inDim, int which)
{
    __nv_bfloat16* hi = (which == 0) ? g_We0[0] : (which == 1) ? g_We1[0] : g_Wd1[0];
    __nv_bfloat16* lo = (which == 0) ? g_We0[1] : (which == 1) ? g_We1[1] : g_Wd1[1];
    float* bd = (which == 0) ? g_be0 : (which == 1) ? g_be1 : g_bd1;
    int K = inDim + 256;
    long idx = (long)blockIdx.x * 256 + threadIdx.x;
    if (idx < (long)K * 1024) {
        int g = (int)(idx / K), k = (int)(idx % K);
        int u = g >> 2, j = g & 3, sr = j * 256 + u;
        float v = (k < inDim) ? Wih[(long)sr * inDim + k] : Whh[(long)sr * 256 + (k - inDim)];
        splitst(hi, lo, idx, v);
    }
    if (idx < 1024) {
        int u = (int)idx >> 2, j = (int)idx & 3;
        bd[idx] = bih[j * 256 + u] + bhh[j * 256 + u];
    }
}
__global__ void prep_d0(const float* Wih, const float* Whh, const float* bih,
                        const float* bhh, const float* fcW, const float* fcb)
{
    long idx = (long)blockIdx.x * 256 + threadIdx.x;
    if (idx < 512l * 1024) {
        int g = (int)(idx >> 9), k = (int)(idx & 511);
        int u = g >> 2, j = g & 3, sr = j * 256 + u;
        float v;
        if (k < 256) {
            float s = 0.f;
            for (int d = 0; d < 128; d++) s += Wih[sr * 128 + d] * fcW[d * 256 + k];
            v = s;
        } else v = Whh[(long)sr * 256 + (k - 256)];
        splitst(g_Wd0[0], g_Wd0[1], idx, v);
    }
    if (idx < 1024) {
        int u = (int)idx >> 2, j = (int)idx & 3, sr = j * 256 + u;
        float bb = bih[sr] + bhh[sr];
        g_bd0t0[idx] = bb;
        float s = 0.f;
        for (int d = 0; d < 128; d++) s += Wih[sr * 128 + d] * fcb[d];
        g_bd0[idx] = bb + s;
    }
}
__global__ void prep_x(const float* x)
{
    long idx = (long)blockIdx.x * 256 + threadIdx.x;
    if (idx < 512l * 256 * 128) {
        long t = idx >> 15, b = (idx >> 7) & 255, d = idx & 127;
        splitst(g_x[0], g_x[1], idx, x[(b * 512 + t) * 128 + d]);
    }
}
__global__ void prep_zero()
{
    long idx = (long)blockIdx.x * 256 + threadIdx.x;
    uint32_t* p = (uint32_t*)&g_hb[0][0][0];
    if (idx < 9l * 2 * HB / 2) p[idx] = 0u;
    if (idx < 8) g_cnt[idx] = 0u;
}
__global__ void prep_fcwt(const float* fcW)
{
    int idx = blockIdx.x * 256 + threadIdx.x;
    if (idx < 256 * 128) g_fcWT[idx] = fcW[(idx & 127) * 256 + (idx >> 7)];
}

// ---- final fc GEMM -----------------------------------------------------------
__global__ void __launch_bounds__(256) out_gemm(const float* __restrict__ fcb,
                                                float* __restrict__ out)
{
    __shared__ float As[32 * 64];
    __shared__ float Bs[64 * 128];
    int tid = threadIdx.x;
    long rowBase = (long)blockIdx.x * 32;
    int dx = tid & 31, ry = tid >> 5;
    float acc[4][4] = {};
    for (int kb = 0; kb < 256; kb += 64) {
        __syncthreads();
#pragma unroll
        for (int j = 0; j < 2; j++) {
            int idx = tid + j * 256; int r = idx >> 4, kq = idx & 15;
            *(float4*)&As[r * 64 + kq * 4] =
                *(const float4*)&g_hist[(rowBase + r) * 256 + kb + kq * 4];
        }
#pragma unroll
        for (int j = 0; j < 8; j++) {
            int idx = tid + j * 256; int k = idx >> 5, dq = idx & 31;
            *(float4*)&Bs[k * 128 + dq * 4] =
                *(const float4*)&g_fcWT[(kb + k) * 128 + dq * 4];
        }
        __syncthreads();
#pragma unroll 4
        for (int k = 0; k < 64; k++) {
            float4 b = *(const float4*)&Bs[k * 128 + dx * 4];
#pragma unroll
            for (int rr = 0; rr < 4; rr++) {
                float a = As[(ry * 4 + rr) * 64 + k];
                acc[rr][0] += a * b.x; acc[rr][1] += a * b.y;
                acc[rr][2] += a * b.z; acc[rr][3] += a * b.w;
            }
        }
    }
    float4 bb = *(const float4*)&fcb[dx * 4];
#pragma unroll
    for (int rr = 0; rr < 4; rr++) {
        long g = rowBase + ry * 4 + rr;
        long b = g & 255, t = g >> 8;
        *(float4*)&out[(b * 512 + t) * 128 + dx * 4] =
            make_float4(acc[rr][0] + bb.x, acc[rr][1] + bb.y,
                        acc[rr][2] + bb.z, acc[rr][3] + bb.w);
    }
}

extern "C" void kernel_launch(void* const* d_in, const int* in_sizes, int n_in,
                              void* d_out, int out_size)
{
    const float* x     = (const float*)d_in[0];
    const float* eWih0 = (const float*)d_in[1],  *eWhh0 = (const float*)d_in[2];
    const float* ebih0 = (const float*)d_in[3],  *ebhh0 = (const float*)d_in[4];
    const float* eWih1 = (const float*)d_in[5],  *eWhh1 = (const float*)d_in[6];
    const float* ebih1 = (const float*)d_in[7],  *ebhh1 = (const float*)d_in[8];
    const float* dWih0 = (const float*)d_in[9],  *dWhh0 = (const float*)d_in[10];
    const float* dbih0 = (const float*)d_in[11], *dbhh0 = (const float*)d_in[12];
    const float* dWih1 = (const float*)d_in[13], *dWhh1 = (const float*)d_in[14];
    const float* dbih1 = (const float*)d_in[15], *dbhh1 = (const float*)d_in[16];
    const float* fcW   = (const float*)d_in[17], *fcb   = (const float*)d_in[18];
    float* out = (float*)d_out;

    prep_w<<<1536, 256>>>(eWih0, eWhh0, ebih0, ebhh0, 128, 0);
    prep_w<<<2048, 256>>>(eWih1, eWhh1, ebih1, ebhh1, 256, 1);
    prep_w<<<2048, 256>>>(dWih1, dWhh1, dbih1, dbhh1, 256, 2);
    prep_d0<<<2048, 256>>>(dWih0, dWhh0, dbih0, dbhh0, fcW, fcb);
    prep_x<<<65536, 256>>>(x);
    prep_zero<<<2304, 256>>>();
    prep_fcwt<<<128, 256>>>(fcW);

    cudaFuncSetAttribute(lstm_mma, cudaFuncAttributeMaxDynamicSharedMemorySize, SMEM_BYTES);
    lstm_mma<<<NB, NT, SMEM_BYTES>>>();

    out_gemm<<<4096, 256>>>(fcb, out);
}

// round 17
// speedup vs baseline: 2.5810x; 1.2344x over previous
#include <cuda_runtime.h>
#include <cuda_fp16.h>
#include <cstdint>

// ============================================================================
// LSTM autoencoder  B=256 T=512 D=128 H=256
// Persistent kernel, 128 CTAs x 256 thr, fp16 mma.sync:
//   A = hi/lo fp16 split (22-bit), W = single fp16, 2 products per k-chunk.
// Per-row-block dataflow sync, cross-phase W prefetch, 4-slot smem ring.
// ============================================================================

#define NB 128
#define NT 256
#define HB 65536   // 256*256 elements per h buffer

// ---- device-global scratch -------------------------------------------------
__device__ __half g_We0[1024 * 384];   // [gatecol][k]
__device__ __half g_We1[1024 * 512];
__device__ __half g_Wd0[1024 * 512];   // k<256: d_Wih0@fc_W, else Whh
__device__ __half g_Wd1[1024 * 512];
__device__ float g_be0[1024], g_be1[1024], g_bd0[1024], g_bd0t0[1024], g_bd1[1024];
__device__ __half g_x[2][512 * 256 * 128];  // [half][(t*256+b)*128+d]
__device__ __half g_hb[9][2][HB];           // 0/1 h1e, 2/3 h2e, 4/5 h1d, 6/7 h2d, 8 zero
__device__ float g_fcWT[256 * 128];
__device__ float g_hist[512ll * HB];
__device__ unsigned g_cnt[8];               // per-row-block phase counters

__device__ __forceinline__ float sigf(float v) { return 1.0f / (1.0f + __expf(-v)); }
__device__ __forceinline__ float tanhf_fast(float v) {
    return 1.0f - 2.0f / (1.0f + __expf(2.0f * v));
}
__device__ __forceinline__ uint32_t smem_u32(const void* p) {
    uint32_t a;
    asm("{ .reg .u64 t; cvta.to.shared.u64 t, %1; cvt.u32.u64 %0, t; }" : "=r"(a) : "l"(p));
    return a;
}

#define CP16(dst, src) do { uint32_t _d = (dst);                              \
    asm volatile("cp.async.cg.shared.global [%0], [%1], 16;" :: "r"(_d), "l"(src)); } while (0)
#define COMMIT() asm volatile("cp.async.commit_group;" ::: "memory")

#define LDSM4(R, ADDR) asm volatile(                                          \
    "ldmatrix.sync.aligned.m8n8.x4.shared.b16 {%0,%1,%2,%3}, [%4];"           \
    : "=r"((R)[0]), "=r"((R)[1]), "=r"((R)[2]), "=r"((R)[3]) : "r"(ADDR))

#define MMA(AC, A, B0, B1) asm volatile(                                      \
    "mma.sync.aligned.m16n8k16.row.col.f32.f16.f16.f32 "                      \
    "{%0,%1,%2,%3},{%4,%5,%6,%7},{%8,%9},{%0,%1,%2,%3};"                      \
    : "+f"((AC)[0]), "+f"((AC)[1]), "+f"((AC)[2]), "+f"((AC)[3])              \
    : "r"((A)[0]), "r"((A)[1]), "r"((A)[2]), "r"((A)[3]), "r"(B0), "r"(B1))

// smem: 4-slot ring; per slot: Ahi[32*144] Alo[32*144] B[64*144] = 18432 B
#define ABUF 4608
#define BBUF 9216
#define BUFB (2*ABUF + BBUF)            // 18432
#define SMEM_BYTES (4 * BUFB)           // 73728

// ---- staging ------------------------------------------------------------------
__device__ __forceinline__ void stage_A(int ch, uint32_t smb,
    const __half* a0h, const __half* a0l, int s0, int k0,
    const __half* a1h, const __half* a1l, int rb, int tid)
{
    int kb = ch << 6;
    const __half *ah, *al; int st, kl;
    if (kb < k0) { ah = a0h; al = a0l; st = s0;  kl = kb; }
    else         { ah = a1h; al = a1l; st = 256; kl = kb - k0; }
    uint32_t base = smb + (ch & 3) * BUFB;
#pragma unroll
    for (int j = 0; j < 2; j++) {                 // 512 x 16B (hi 256 + lo 256)
        int idx = tid + j * NT;
        int hf = idx >> 8, r = (idx >> 3) & 31, p = idx & 7;
        const __half* src = (hf ? al : ah) + (long)(rb * 32 + r) * st + kl + p * 8;
        CP16(base + hf * ABUF + r * 144 + p * 16, src);
    }
}
__device__ __forceinline__ void stage_B(int ch, uint32_t smb,
    const __half* W, int K, int gb, int tid)
{
    int kb = ch << 6;
    uint32_t base = smb + (ch & 3) * BUFB + 2 * ABUF;
#pragma unroll
    for (int j = 0; j < 2; j++) {                 // 512 x 16B
        int idx = tid + j * NT;
        int n = idx >> 3, p = idx & 7;
        const __half* src = W + (long)(gb * 64 + n) * K + kb + p * 8;
        CP16(base + n * 144 + p * 16, src);
    }
}

__device__ __forceinline__ void rb_wait(unsigned target, int rb, int tid)
{
    if (tid == 0) {
        while (*(volatile unsigned*)&g_cnt[rb] < target) { }
        __threadfence();
    }
    __syncthreads();
}

// ---- one LSTM phase -------------------------------------------------------------
__device__ __forceinline__ void run_phase(
    const __half* a0h, const __half* a0l, int s0, int k0,
    const __half* a1h, const __half* a1l,
    const __half* W, int K,
    const __half* nW, int nK,
    const float* bias,
    __half* ohi, __half* olo, float* of32, float* c,
    uint32_t smb, uint32_t laneA, uint32_t laneB,
    int rb, int gb, int tid, bool first)
{
    int nt = K >> 6;
    if (first) {   // no carried prefetch: stage B chunks 0,1 (2 groups)
        stage_B(0, smb, W, K, gb, tid); COMMIT();
        stage_B(1, smb, W, K, gb, tid); COMMIT();
    }
    stage_A(0, smb, a0h, a0l, s0, k0, a1h, a1l, rb, tid); COMMIT();
    stage_A(1, smb, a0h, a0l, s0, k0, a1h, a1l, rb, tid); COMMIT();
    stage_A(2, smb, a0h, a0l, s0, k0, a1h, a1l, rb, tid);
    stage_B(2, smb, W, K, gb, tid); COMMIT();

    float acc0[4] = {0.f, 0.f, 0.f, 0.f};
    float acc1[4] = {0.f, 0.f, 0.f, 0.f};

    for (int i = 0; i < nt; i++) {
        int wg = nt - 1 - i;
        if (wg >= 2)      asm volatile("cp.async.wait_group 2;" ::: "memory");
        else if (wg == 1) asm volatile("cp.async.wait_group 1;" ::: "memory");
        else              asm volatile("cp.async.wait_group 0;" ::: "memory");
        __syncthreads();

        if (i + 3 < nt) {   // slot (i+3)&3 == (i-1)&3: reads done before this sync
            stage_A(i + 3, smb, a0h, a0l, s0, k0, a1h, a1l, rb, tid);
            stage_B(i + 3, smb, W, K, gb, tid);
            COMMIT();
        }

        uint32_t base = smb + (i & 3) * BUFB;
        uint32_t aH = base + laneA;
        uint32_t aL = aH + ABUF;
        uint32_t bB = base + 2 * ABUF + laneB;
#pragma unroll
        for (int ks = 0; ks < 4; ks++) {
            uint32_t ra[4], la[4], rb4[4];
            LDSM4(ra,  aH + ks * 32);
            LDSM4(la,  aL + ks * 32);
            LDSM4(rb4, bB + ks * 32);
            MMA(acc0, ra, rb4[0], rb4[1]);
            MMA(acc0, la, rb4[0], rb4[1]);
            MMA(acc1, ra, rb4[2], rb4[3]);
            MMA(acc1, la, rb4[2], rb4[3]);
        }
    }

    // tail: prefetch NEXT phase's weight chunks 0,1 (needs all reads of slots 0,1 done)
    __syncthreads();
    if (nW) {
        stage_B(0, smb, nW, nK, gb, tid); COMMIT();
        stage_B(1, smb, nW, nK, gb, tid); COMMIT();
    }

    // epilogue: pair (i,f)/(g,o) lanes via shfl, LSTM cell, write h
    int l = tid & 31, w = tid >> 5;
    int rh = w & 1, wc = w >> 1;
    int g = l >> 2, t4 = l & 3;
    int odd = t4 & 1;
#pragma unroll
    for (int n2 = 0; n2 < 2; n2++) {
        float* A = n2 ? acc1 : acc0;
        float s0v = odd ? A[0] : A[2];
        float s1v = odd ? A[1] : A[3];
        float r0 = __shfl_xor_sync(0xFFFFFFFFu, s0v, 1);
        float r1 = __shfl_xor_sync(0xFFFFFFFFu, s1v, 1);
        float iv, fv, gv, ov; int rowC;
        if (!odd) { iv = A[0]; fv = A[1]; gv = r0;   ov = r1;   rowC = rh * 16 + g; }
        else      { iv = r0;   fv = r1;   gv = A[2]; ov = A[3]; rowC = rh * 16 + g + 8; }
        int unit = wc * 4 + n2 * 2 + (t4 >> 1);
        float4 bv = *(const float4*)&bias[gb * 64 + unit * 4];
        iv += bv.x; fv += bv.y; gv += bv.z; ov += bv.w;
        float cn = sigf(fv) * c[n2] + sigf(iv) * tanhf_fast(gv);
        c[n2] = cn;
        float h = sigf(ov) * tanhf_fast(cn);
        int row = rb * 32 + rowC, uG = gb * 16 + unit;
        __half hh = __float2half_rn(h);
        ohi[row * 256 + uG] = hh;
        olo[row * 256 + uG] = __float2half_rn(h - __half2float(hh));
        if (of32) of32[row * 256 + uG] = h;
    }

    // release: make h visible, then signal this row-block
    __threadfence();
    __syncthreads();
    if (tid == 0) atomicAdd(&g_cnt[rb], 1u);
}

// ---- persistent kernel ------------------------------------------------------------
__global__ void __launch_bounds__(NT, 1) lstm_mma()
{
    extern __shared__ char sm[];
    uint32_t smb = smem_u32(sm);
    int tid = threadIdx.x, bid = blockIdx.x;
    int rb = bid & 7;        // 8 row blocks of 32
    int gb = bid >> 3;       // 16 gate blocks of 64
    int l = tid & 31, w = tid >> 5;
    int rh = w & 1, wc = w >> 1;
    uint32_t laneA = (uint32_t)((rh * 16 + (l & 15)) * 144 + ((l >> 4) & 1) * 16);
    uint32_t laneB = (uint32_t)((wc * 16 + ((l >> 4) & 1) * 8 + (l & 7)) * 144
                                + ((l >> 3) & 1) * 16);

    float c1[2] = {0.f, 0.f}, c2[2] = {0.f, 0.f};
    unsigned target = 0;
    bool first = true;

    for (int t = 0; t < 512; t++) {
        int cur = t & 1, prv = cur ^ 1;
        rb_wait(target, rb, tid);
        run_phase(g_x[0] + (long)t * 32768, g_x[1] + (long)t * 32768, 128, 128,
                  g_hb[prv][0], g_hb[prv][1],
                  g_We0, 384, g_We1, 512,
                  g_be0, g_hb[cur][0], g_hb[cur][1], nullptr, c1,
                  smb, laneA, laneB, rb, gb, tid, first);
        first = false;
        target += 16;

        rb_wait(target, rb, tid);
        const __half* nw; int nk;
        if (t < 511) { nw = g_We0; nk = 384; }
        else         { nw = g_Wd0; nk = 512; }
        run_phase(g_hb[cur][0], g_hb[cur][1], 256, 256,
                  g_hb[2 + prv][0], g_hb[2 + prv][1],
                  g_We1, 512, nw, nk,
                  g_be1, g_hb[2 + cur][0], g_hb[2 + cur][1], nullptr, c2,
                  smb, laneA, laneB, rb, gb, tid, false);
        target += 16;
    }

    for (int t = 0; t < 512; t++) {
        int cur = t & 1, prv = cur ^ 1;
        const __half* i0h = (t == 0) ? g_hb[8][0] : g_hb[6 + prv][0];
        const __half* i0l = (t == 0) ? g_hb[8][1] : g_hb[6 + prv][1];
        const __half* h1h = (t == 0) ? g_hb[1][0] : g_hb[4 + prv][0];
        const __half* h1l = (t == 0) ? g_hb[1][1] : g_hb[4 + prv][1];
        const __half* h2h = (t == 0) ? g_hb[3][0] : g_hb[6 + prv][0];
        const __half* h2l = (t == 0) ? g_hb[3][1] : g_hb[6 + prv][1];
        const float* b0 = (t == 0) ? g_bd0t0 : g_bd0;

        rb_wait(target, rb, tid);
        run_phase(i0h, i0l, 256, 256, h1h, h1l,
                  g_Wd0, 512, g_Wd1, 512,
                  b0, g_hb[4 + cur][0], g_hb[4 + cur][1], nullptr, c1,
                  smb, laneA, laneB, rb, gb, tid, false);
        target += 16;

        rb_wait(target, rb, tid);
        const __half* nw = (t < 511) ? g_Wd0 : nullptr;
        run_phase(g_hb[4 + cur][0], g_hb[4 + cur][1], 256, 256, h2h, h2l,
                  g_Wd1, 512, nw, 512,
                  g_bd1, g_hb[6 + cur][0], g_hb[6 + cur][1], g_hist + (long)t * HB, c2,
                  smb, laneA, laneB, rb, gb, tid, false);
        target += 16;
    }
}

// ---- prep ---------------------------------------------------------------------
__device__ __forceinline__ void split_h(__half* hi, __half* lo, long i, float v) {
    __half h = __float2half_rn(v);
    hi[i] = h; lo[i] = __float2half_rn(v - __half2float(h));
}
__global__ void prep_w(const float* Wih, const float* Whh, const float* bih,
                       const float* bhh, int inDim, int which)
{
    __half* Wd = (which == 0) ? g_We0 : (which == 1) ? g_We1 : g_Wd1;
    float* bd = (which == 0) ? g_be0 : (which == 1) ? g_be1 : g_bd1;
    int K = inDim + 256;
    long idx = (long)blockIdx.x * 256 + threadIdx.x;
    if (idx < (long)K * 1024) {
        int g = (int)(idx / K), k = (int)(idx % K);
        int u = g >> 2, j = g & 3, sr = j * 256 + u;
        float v = (k < inDim) ? Wih[(long)sr * inDim + k] : Whh[(long)sr * 256 + (k - inDim)];
        Wd[idx] = __float2half_rn(v);
    }
    if (idx < 1024) {
        int u = (int)idx >> 2, j = (int)idx & 3;
        bd[idx] = bih[j * 256 + u] + bhh[j * 256 + u];
    }
}
__global__ void prep_d0(const float* Wih, const float* Whh, const float* bih,
                        const float* bhh, const float* fcW, const float* fcb)
{
    long idx = (long)blockIdx.x * 256 + threadIdx.x;
    if (idx < 512l * 1024) {
        int g = (int)(idx >> 9), k = (int)(idx & 511);
        int u = g >> 2, j = g & 3, sr = j * 256 + u;
        float v;
        if (k < 256) {
            float s = 0.f;
            for (int d = 0; d < 128; d++) s += Wih[sr * 128 + d] * fcW[d * 256 + k];
            v = s;
        } else v = Whh[(long)sr * 256 + (k - 256)];
        g_Wd0[idx] = __float2half_rn(v);
    }
    if (idx < 1024) {
        int u = (int)idx >> 2, j = (int)idx & 3, sr = j * 256 + u;
        float bb = bih[sr] + bhh[sr];
        g_bd0t0[idx] = bb;
        float s = 0.f;
        for (int d = 0; d < 128; d++) s += Wih[sr * 128 + d] * fcb[d];
        g_bd0[idx] = bb + s;
    }
}
__global__ void prep_x(const float* x)
{
    long idx = (long)blockIdx.x * 256 + threadIdx.x;
    if (idx < 512l * 256 * 128) {
        long t = idx >> 15, b = (idx >> 7) & 255, d = idx & 127;
        split_h(g_x[0], g_x[1], idx, x[(b * 512 + t) * 128 + d]);
    }
}
__global__ void prep_zero()
{
    long idx = (long)blockIdx.x * 256 + threadIdx.x;
    uint32_t* p = (uint32_t*)&g_hb[0][0][0];
    if (idx < 9l * 2 * HB / 2) p[idx] = 0u;
    if (idx < 8) g_cnt[idx] = 0u;
}
__global__ void prep_fcwt(const float* fcW)
{
    int idx = blockIdx.x * 256 + threadIdx.x;
    if (idx < 256 * 128) g_fcWT[idx] = fcW[(idx & 127) * 256 + (idx >> 7)];
}

// ---- final fc GEMM ----------------------------------------------------------
__global__ void __launch_bounds__(256) out_gemm(const float* __restrict__ fcb,
                                                float* __restrict__ out)
{
    __shared__ float As[32 * 64];
    __shared__ float Bs[64 * 128];
    int tid = threadIdx.x;
    long rowBase = (long)blockIdx.x * 32;
    int dx = tid & 31, ry = tid >> 5;
    float acc[4][4] = {};
    for (int kb = 0; kb < 256; kb += 64) {
        __syncthreads();
#pragma unroll
        for (int j = 0; j < 2; j++) {
            int idx = tid + j * 256; int r = idx >> 4, kq = idx & 15;
            *(float4*)&As[r * 64 + kq * 4] =
                *(const float4*)&g_hist[(rowBase + r) * 256 + kb + kq * 4];
        }
#pragma unroll
        for (int j = 0; j < 8; j++) {
            int idx = tid + j * 256; int k = idx >> 5, dq = idx & 31;
            *(float4*)&Bs[k * 128 + dq * 4] =
                *(const float4*)&g_fcWT[(kb + k) * 128 + dq * 4];
        }
        __syncthreads();
#pragma unroll 4
        for (int k = 0; k < 64; k++) {
            float4 b = *(const float4*)&Bs[k * 128 + dx * 4];
#pragma unroll
            for (int rr = 0; rr < 4; rr++) {
                float a = As[(ry * 4 + rr) * 64 + k];
                acc[rr][0] += a * b.x; acc[rr][1] += a * b.y;
                acc[rr][2] += a * b.z; acc[rr][3] += a * b.w;
            }
        }
    }
    float4 bb = *(const float4*)&fcb[dx * 4];
#pragma unroll
    for (int rr = 0; rr < 4; rr++) {
        long g = rowBase + ry * 4 + rr;
        long b = g & 255, t = g >> 8;
        *(float4*)&out[(b * 512 + t) * 128 + dx * 4] =
            make_float4(acc[rr][0] + bb.x, acc[rr][1] + bb.y,
                        acc[rr][2] + bb.z, acc[rr][3] + bb.w);
    }
}

extern "C" void kernel_launch(void* const* d_in, const int* in_sizes, int n_in,
                              void* d_out, int out_size)
{
    const float* x     = (const float*)d_in[0];
    const float* eWih0 = (const float*)d_in[1],  *eWhh0 = (const float*)d_in[2];
    const float* ebih0 = (const float*)d_in[3],  *ebhh0 = (const float*)d_in[4];
    const float* eWih1 = (const float*)d_in[5],  *eWhh1 = (const float*)d_in[6];
    const float* ebih1 = (const float*)d_in[7],  *ebhh1 = (const float*)d_in[8];
    const float* dWih0 = (const float*)d_in[9],  *dWhh0 = (const float*)d_in[10];
    const float* dbih0 = (const float*)d_in[11], *dbhh0 = (const float*)d_in[12];
    const float* dWih1 = (const float*)d_in[13], *dWhh1 = (const float*)d_in[14];
    const float* dbih1 = (const float*)d_in[15], *dbhh1 = (const float*)d_in[16];
    const float* fcW   = (const float*)d_in[17], *fcb   = (const float*)d_in[18];
    float* out = (float*)d_out;

    prep_w<<<1536, 256>>>(eWih0, eWhh0, ebih0, ebhh0, 128, 0);
    prep_w<<<2048, 256>>>(eWih1, eWhh1, ebih1, ebhh1, 256, 1);
    prep_w<<<2048, 256>>>(dWih1, dWhh1, dbih1, dbhh1, 256, 2);
    prep_d0<<<2048, 256>>>(dWih0, dWhh0, dbih0, dbhh0, fcW, fcb);
    prep_x<<<65536, 256>>>(x);
    prep_zero<<<2304, 256>>>();
    prep_fcwt<<<128, 256>>>(fcW);

    cudaFuncSetAttribute(lstm_mma, cudaFuncAttributeMaxDynamicSharedMemorySize, SMEM_BYTES);
    lstm_mma<<<NB, NT, SMEM_BYTES>>>();

    out_gemm<<<4096, 256>>>(fcb, out);
}